// round 5
// baseline (speedup 1.0000x reference)
#include <cuda_runtime.h>

// FilterLayer: y[b,c,h,w] = sum_{i,j in 5x5} x_pad[b,c,h+i,w+j] * f[b,i*5+j,h,w]
// B=4, C=3, H=W=512, window=5, zero pad 2.
// R5: FULL-WIDTH row tiles for DRAM page locality. One image row = 2KB = ~one
// HBM page; narrow tiles (R2/R4) split each page across 8-16 blocks -> page
// opened many times -> hard ~55% DRAM ceiling. Here each block consumes whole
// contiguous rows of f/x/out, so every page opens once.
// Shape: 512 threads/block, tile = 2 rows x 512 px, 2 px/thread (float2).

#define IMG_H 512
#define IMG_W 512
#define TH 2                      // output rows per block
#define HALO 2
#define TILE_R (TH + 2 * HALO)    // 6
#define TILE_C (IMG_W + 4)        // 516 (tap reaches p0+5, max 515)
#define NTHREADS 512

__global__ __launch_bounds__(NTHREADS)
void filter_layer_kernel(const float* __restrict__ x,
                         const float* __restrict__ f,
                         float* __restrict__ out)
{
    __shared__ __align__(8) float xs[3][TILE_R][TILE_C];

    const int b   = blockIdx.z;
    const int h0  = blockIdx.y * TH;
    const int tid = threadIdx.x;
    const int row = tid >> 8;         // 0..1
    const int tx  = tid & 255;        // 0..255  -> pixels 2tx, 2tx+1

    const int HW  = IMG_H * IMG_W;
    const int W2  = IMG_W / 2;        // 256
    const int HW2 = HW / 2;

    // ---- Stage 3-channel x rows [h0-2, h0+3] full width (zero-padded) ----
    const float* xb = x + (size_t)b * 3 * HW;
    for (int idx = tid; idx < 3 * TILE_R * TILE_C; idx += NTHREADS) {
        int c   = idx / (TILE_R * TILE_C);
        int rem = idx - c * (TILE_R * TILE_C);
        int r   = rem / TILE_C;
        int col = rem - r * TILE_C;
        int gr  = h0 + r - HALO;
        int gc  = col - HALO;
        float v = 0.0f;
        if ((unsigned)gr < (unsigned)IMG_H && (unsigned)gc < (unsigned)IMG_W)
            v = __ldg(xb + c * HW + gr * IMG_W + gc);
        xs[c][r][col] = v;
    }
    __syncthreads();

    // ---- 2 pixels per thread in row h0+row: local cols p0, p0+1 ----
    const int h  = h0 + row;
    const int p0 = 2 * tx;
    const float2* f2 = (const float2*)(f + (size_t)b * 25 * HW);
    const int fbase = h * W2 + tx;

    float2 a0 = make_float2(0.f, 0.f);
    float2 a1 = a0, a2 = a0;

    #pragma unroll
    for (int i = 0; i < 5; ++i) {
        // 6 consecutive smem floats per channel, 8B-aligned -> 3x LDS.64 each
        float xr0[6], xr1[6], xr2[6];
        {
            const float2* r0 = (const float2*)&xs[0][row + i][p0];
            const float2* r1 = (const float2*)&xs[1][row + i][p0];
            const float2* r2 = (const float2*)&xs[2][row + i][p0];
            float2 u;
            u = r0[0]; xr0[0]=u.x; xr0[1]=u.y;
            u = r0[1]; xr0[2]=u.x; xr0[3]=u.y;
            u = r0[2]; xr0[4]=u.x; xr0[5]=u.y;
            u = r1[0]; xr1[0]=u.x; xr1[1]=u.y;
            u = r1[1]; xr1[2]=u.x; xr1[3]=u.y;
            u = r1[2]; xr1[4]=u.x; xr1[5]=u.y;
            u = r2[0]; xr2[0]=u.x; xr2[1]=u.y;
            u = r2[1]; xr2[2]=u.x; xr2[3]=u.y;
            u = r2[2]; xr2[4]=u.x; xr2[5]=u.y;
        }
        #pragma unroll
        for (int j = 0; j < 5; ++j) {
            const int k = i * 5 + j;
            const float2 fv = __ldcs(f2 + (size_t)k * HW2 + fbase);
            a0.x = fmaf(xr0[j    ], fv.x, a0.x);
            a0.y = fmaf(xr0[j + 1], fv.y, a0.y);
            a1.x = fmaf(xr1[j    ], fv.x, a1.x);
            a1.y = fmaf(xr1[j + 1], fv.y, a1.y);
            a2.x = fmaf(xr2[j    ], fv.x, a2.x);
            a2.y = fmaf(xr2[j + 1], fv.y, a2.y);
        }
    }

    // streaming stores: out is written once, keep L2 for x
    float2* o2 = (float2*)(out + (size_t)b * 3 * HW);
    const int obase = h * W2 + tx;
    __stcs(o2 + obase,           a0);
    __stcs(o2 + obase + HW2,     a1);
    __stcs(o2 + obase + 2 * HW2, a2);
}

extern "C" void kernel_launch(void* const* d_in, const int* in_sizes, int n_in,
                              void* d_out, int out_size)
{
    const float* x = (const float*)d_in[0];
    const float* f = (const float*)d_in[1];
    float* out = (float*)d_out;

    dim3 block(NTHREADS, 1, 1);                // 512 threads
    dim3 grid(1, IMG_H / TH, 4);               // 1 x 256 x 4 = 1024 blocks
    filter_layer_kernel<<<grid, block>>>(x, f, out);
}